// round 3
// baseline (speedup 1.0000x reference)
#include <cuda_runtime.h>
#include <cstdint>

#define NEG_CLAMP -20.0f
#define EPSV 1e-6f

static constexpr int Bb = 8, Ll = 4096, Hh = 16, Ee = 64;
static constexpr int BH = Bb * Hh;        // 128
static constexpr int RS = Hh * Ee;        // row stride in floats = 1024
static constexpr int SPLIT = 8;
static constexpr int ROWS1 = Ll / SPLIT;  // 512 rows per pass-1 block
static constexpr int TILE1 = 64;

// scratch (static device arrays: allowed; runtime alloc is not)
__device__ float g_kv_part[SPLIT * BH * Ee * Ee];
__device__ float g_ks_part[SPLIT * BH * Ee];
__device__ float g_kv[BH * Ee * Ee];
__device__ float g_ks[BH * Ee];

typedef unsigned long long u64;

__device__ __forceinline__ u64 pack2(float x, float y) {
    u64 r; asm("mov.b64 %0, {%1, %2};" : "=l"(r) : "f"(x), "f"(y)); return r;
}
__device__ __forceinline__ float2 unpack2(u64 v) {
    float2 r; asm("mov.b64 {%0, %1}, %2;" : "=f"(r.x), "=f"(r.y) : "l"(v)); return r;
}
// Blackwell packed fp32 FMA (2 FMAs/instr -> 128 FMA/SM/cyc vs 64 for FFMA-3reg)
__device__ __forceinline__ u64 ffma2(u64 a, u64 b, u64 c) {
    u64 d; asm("fma.rn.f32x2 %0, %1, %2, %3;" : "=l"(d) : "l"(a), "l"(b), "l"(c)); return d;
}
__device__ __forceinline__ u64 fmul2(u64 a, u64 b) {
    u64 d; asm("mul.rn.f32x2 %0, %1, %2;" : "=l"(d) : "l"(a), "l"(b)); return d;
}

// Permuted layout for rows of 64 duplicated 8-byte pairs (32 x 16B units per row).
// unit u (0..31) placed at 16B slot (u&3)*8 + (u>>2), so a warp whose lanes index
// consecutive "groups of 4 units" reads 128B-contiguous, conflict-free.
// Returns offset of pair p (0..63) in 8-byte units within the 512B row.
__device__ __forceinline__ int dup_off8(int p) {
    int u = p >> 1, h = p & 1;
    return ((((u & 3) << 3) + (u >> 2)) << 1) + h;
}

__device__ __forceinline__ float warp_sum(float v) {
    #pragma unroll
    for (int o = 16; o > 0; o >>= 1) v += __shfl_xor_sync(0xffffffffu, v, o);
    return v;
}

// ---------------------------------------------------------------------------
// Pass 1: per (head, L-split): KV_partial = phi(K)^T V  (64x64), ksum_partial
// ---------------------------------------------------------------------------
__global__ void __launch_bounds__(256) k_pass1(const float* __restrict__ Kin,
                                               const float* __restrict__ Vin,
                                               const float* __restrict__ D1) {
    __shared__ __align__(16) float s_kd[TILE1 * 128]; // dup phi(k): 64 rows x 512B = 32KB
    __shared__ __align__(16) float s_v[TILE1 * 64];   // v tile: 16KB (permuted units)

    const int bh = blockIdx.x / SPLIT, sp = blockIdx.x % SPLIT;
    const int b = bh >> 4, h = bh & 15;
    const int tid = threadIdx.x, w = tid >> 5, lane = tid & 31;
    const int g = tid >> 6, t = tid & 63, eg = t >> 3, dg = t & 7;

    const float invT = 1.0f / log1pf(__expf(*D1));
    const long base = (long)b * Ll * RS + h * Ee;

    u64 acc[8][4]; // e (8) x d-pair (4) register tile, group covers 64x64
    #pragma unroll
    for (int i = 0; i < 8; i++)
        #pragma unroll
        for (int j = 0; j < 4; j++) acc[i][j] = 0ull;
    float ks0 = 0.f, ks1 = 0.f;

    const int l00 = sp * ROWS1;
    for (int tile = 0; tile < ROWS1 / TILE1; tile++) {
        const int l0 = l00 + tile * TILE1;

        // stage V tile with permuted 16B units
        #pragma unroll
        for (int i = 0; i < 4; i++) {
            int lin = tid + 256 * i;
            int r = lin >> 4, q = lin & 15;
            float4 vv = *(const float4*)(Vin + base + (long)(l0 + r) * RS + q * 4);
            int off16 = ((q & 1) << 3) + (q >> 1);
            *(float4*)(s_v + r * 64 + off16 * 4) = vv;
        }
        // softmax(K) rows -> duplicated pairs. warp w handles rows w, w+8, ...
        #pragma unroll
        for (int i = 0; i < 8; i++) {
            int r = w + 8 * i;
            const float* kp = Kin + base + (long)(l0 + r) * RS;
            float x0 = kp[lane], x1 = kp[lane + 32];
            x0 = x0 < 0.f ? NEG_CLAMP : x0;
            x1 = x1 < 0.f ? NEG_CLAMP : x1;
            float e0 = __expf(x0 * invT), e1 = __expf(x1 * invT);
            float rs = 1.0f / warp_sum(e0 + e1);
            e0 *= rs; e1 *= rs;
            ks0 += e0; ks1 += e1;
            *(u64*)(s_kd + r * 128 + dup_off8(lane) * 2)      = pack2(e0, e0);
            *(u64*)(s_kd + r * 128 + dup_off8(lane + 32) * 2) = pack2(e1, e1);
        }
        __syncthreads();

        // rank-1 update accumulation: group g handles rows 16g..16g+15
        #pragma unroll 1
        for (int rr = 0; rr < 16; rr++) {
            const float* kr = s_kd + (g * 16 + rr) * 128;
            const float* vr = s_v  + (g * 16 + rr) * 64;
            ulonglong2 kd0 = *(const ulonglong2*)(kr + (0 * 8 + eg) * 4);
            ulonglong2 kd1 = *(const ulonglong2*)(kr + (1 * 8 + eg) * 4);
            ulonglong2 kd2 = *(const ulonglong2*)(kr + (2 * 8 + eg) * 4);
            ulonglong2 kd3 = *(const ulonglong2*)(kr + (3 * 8 + eg) * 4);
            u64 kk[8] = {kd0.x, kd0.y, kd1.x, kd1.y, kd2.x, kd2.y, kd3.x, kd3.y};
            ulonglong2 vp0 = *(const ulonglong2*)(vr + (0 * 8 + dg) * 4);
            ulonglong2 vp1 = *(const ulonglong2*)(vr + (1 * 8 + dg) * 4);
            u64 vv2[4] = {vp0.x, vp0.y, vp1.x, vp1.y};
            #pragma unroll
            for (int e = 0; e < 8; e++)
                #pragma unroll
                for (int dp = 0; dp < 4; dp++)
                    acc[e][dp] = ffma2(kk[e], vv2[dp], acc[e][dp]);
        }
        __syncthreads();
    }

    // deterministic in-block reduction over the 4 groups (fixed order)
    float* KVsh = s_kd; // reuse, viewed as KV[64][64]
    for (int gg = 0; gg < 4; gg++) {
        if (g == gg) {
            #pragma unroll
            for (int e = 0; e < 8; e++)
                #pragma unroll
                for (int dp = 0; dp < 4; dp++) {
                    float2 a = unpack2(acc[e][dp]);
                    float* p = KVsh + (8 * eg + e) * 64 + 8 * dg + 2 * dp;
                    if (gg == 0) { p[0] = a.x;  p[1] = a.y; }
                    else         { p[0] += a.x; p[1] += a.y; }
                }
        }
        __syncthreads();
    }
    float* dst = g_kv_part + ((long)sp * BH + bh) * (Ee * Ee);
    #pragma unroll
    for (int i = 0; i < 4; i++) {
        int i4 = tid + 256 * i;
        *(float4*)(dst + i4 * 4) = *(const float4*)(KVsh + i4 * 4);
    }
    // ksum: per-warp registers -> shared -> partial
    float* kss = s_v; // reuse
    kss[w * 64 + lane] = ks0;
    kss[w * 64 + lane + 32] = ks1;
    __syncthreads();
    if (tid < 64) {
        float s = 0.f;
        #pragma unroll
        for (int ww = 0; ww < 8; ww++) s += kss[ww * 64 + tid];
        g_ks_part[((long)sp * BH + bh) * Ee + tid] = s;
    }
}

// ---------------------------------------------------------------------------
// Deterministic split reduction
// ---------------------------------------------------------------------------
__global__ void __launch_bounds__(256) k_reduce() {
    const int bh = blockIdx.x, tid = threadIdx.x;
    for (int i = tid; i < Ee * Ee; i += 256) {
        float s = 0.f;
        #pragma unroll
        for (int sp = 0; sp < SPLIT; sp++)
            s += g_kv_part[((long)sp * BH + bh) * (Ee * Ee) + i];
        g_kv[(long)bh * (Ee * Ee) + i] = s;
    }
    if (tid < Ee) {
        float s = 0.f;
        #pragma unroll
        for (int sp = 0; sp < SPLIT; sp++)
            s += g_ks_part[((long)sp * BH + bh) * Ee + tid];
        g_ks[(long)bh * Ee + tid] = s;
    }
}

// ---------------------------------------------------------------------------
// Pass 2: out_l = (phi(q_l) . KV) * z_l,  z_l = 1/(phi(q_l).ksum + eps)
// 4096 blocks, each: one head x 128 rows
// ---------------------------------------------------------------------------
__global__ void __launch_bounds__(256) k_pass2(const float* __restrict__ Qin,
                                               float* __restrict__ Out,
                                               const float* __restrict__ D1) {
    extern __shared__ __align__(16) float sm[];
    float* s_kv = sm;           // 8192 floats: KV duplicated pairs (permuted)
    float* s_qT = sm + 8192;    // 64*130: phi(q) transposed, stride 130
    float* s_z  = s_qT + 8320;  // 128
    float* s_ks = s_z + 128;    // 64

    const int bh = blockIdx.x >> 5, chunk = blockIdx.x & 31;
    const int b = bh >> 4, h = bh & 15;
    const int tid = threadIdx.x, w = tid >> 5, lane = tid & 31;
    const float invT = 1.0f / log1pf(__expf(*D1));
    const long base = (long)b * Ll * RS + h * Ee;
    const int l0 = chunk * 128;

    // stage duplicated KV
    const float* kvsrc = g_kv + (long)bh * (Ee * Ee);
    #pragma unroll
    for (int i = 0; i < 4; i++) {
        int i4 = tid + 256 * i;
        float4 v4 = *(const float4*)(kvsrc + i4 * 4);
        int e = i4 >> 4, q = i4 & 15;
        float* rowb = s_kv + e * 128;
        *(u64*)(rowb + dup_off8(q * 4 + 0) * 2) = pack2(v4.x, v4.x);
        *(u64*)(rowb + dup_off8(q * 4 + 1) * 2) = pack2(v4.y, v4.y);
        *(u64*)(rowb + dup_off8(q * 4 + 2) * 2) = pack2(v4.z, v4.z);
        *(u64*)(rowb + dup_off8(q * 4 + 3) * 2) = pack2(v4.w, v4.w);
    }
    if (tid < 64) s_ks[tid] = g_ks[(long)bh * Ee + tid];
    __syncthreads();

    // softmax(Q) -> transposed shared + z. warp w handles rows w, w+8, ...
    float ksA = s_ks[lane], ksB = s_ks[lane + 32];
    #pragma unroll
    for (int i = 0; i < 16; i++) {
        int r = w + 8 * i;
        const float* qp = Qin + base + (long)(l0 + r) * RS;
        float x0 = qp[lane], x1 = qp[lane + 32];
        x0 = x0 < 0.f ? NEG_CLAMP : x0;
        x1 = x1 < 0.f ? NEG_CLAMP : x1;
        float e0 = __expf(x0 * invT), e1 = __expf(x1 * invT);
        float rs = 1.0f / warp_sum(e0 + e1);
        e0 *= rs; e1 *= rs;
        s_qT[lane * 130 + r]        = e0;
        s_qT[(lane + 32) * 130 + r] = e1;
        float dot = warp_sum(e0 * ksA + e1 * ksB);
        if (lane == 0) s_z[r] = 1.0f / (dot + EPSV);
    }
    __syncthreads();

    // matmul: group g -> rows 32g..32g+31; thread: 4 rows (2 packed pairs) x 8 d
    const int g = tid >> 6, t = tid & 63, rg = t >> 3, dg = t & 7;
    const int rb = g * 32 + rg * 4;
    u64 acc[2][8];
    #pragma unroll
    for (int p = 0; p < 2; p++)
        #pragma unroll
        for (int j = 0; j < 8; j++) acc[p][j] = 0ull;

    #pragma unroll 4
    for (int e = 0; e < 64; e++) {
        const float* qc = s_qT + e * 130 + rb;
        u64 q0 = *(const u64*)qc;        // rows rb, rb+1
        u64 q1 = *(const u64*)(qc + 2);  // rows rb+2, rb+3
        const float* kr = s_kv + e * 128;
        ulonglong2 a0 = *(const ulonglong2*)(kr + (0 * 8 + dg) * 4);
        ulonglong2 a1 = *(const ulonglong2*)(kr + (1 * 8 + dg) * 4);
        ulonglong2 a2 = *(const ulonglong2*)(kr + (2 * 8 + dg) * 4);
        ulonglong2 a3 = *(const ulonglong2*)(kr + (3 * 8 + dg) * 4);
        u64 kv8[8] = {a0.x, a0.y, a1.x, a1.y, a2.x, a2.y, a3.x, a3.y};
        #pragma unroll
        for (int j = 0; j < 8; j++) {
            acc[0][j] = ffma2(q0, kv8[j], acc[0][j]);
            acc[1][j] = ffma2(q1, kv8[j], acc[1][j]);
        }
    }

    u64 zp[2];
    zp[0] = *(const u64*)(s_z + rb);
    zp[1] = *(const u64*)(s_z + rb + 2);
    #pragma unroll
    for (int p = 0; p < 2; p++) {
        float2 r2[8];
        #pragma unroll
        for (int j = 0; j < 8; j++) r2[j] = unpack2(fmul2(acc[p][j], zp[p]));
        float* o = Out + base + (long)(l0 + rb + 2 * p) * RS + 8 * dg;
        float4 f;
        f.x = r2[0].x; f.y = r2[1].x; f.z = r2[2].x; f.w = r2[3].x; *(float4*)(o)     = f;
        f.x = r2[4].x; f.y = r2[5].x; f.z = r2[6].x; f.w = r2[7].x; *(float4*)(o + 4) = f;
        o += RS; // next row (hi lanes)
        f.x = r2[0].y; f.y = r2[1].y; f.z = r2[2].y; f.w = r2[3].y; *(float4*)(o)     = f;
        f.x = r2[4].y; f.y = r2[5].y; f.z = r2[6].y; f.w = r2[7].y; *(float4*)(o + 4) = f;
    }
}

extern "C" void kernel_launch(void* const* d_in, const int* in_sizes, int n_in,
                              void* d_out, int out_size) {
    const float* Q  = (const float*)d_in[0];
    const float* K  = (const float*)d_in[1];
    const float* V  = (const float*)d_in[2];
    const float* D1 = (const float*)d_in[3];
    float* O = (float*)d_out;

    const int smem2 = (8192 + 8320 + 128 + 64) * 4; // 66816 B > 48KB -> opt-in
    cudaFuncSetAttribute(k_pass2, cudaFuncAttributeMaxDynamicSharedMemorySize, smem2);

    k_pass1 <<<BH * SPLIT, 256>>>(K, V, D1);
    k_reduce<<<BH, 256>>>();
    k_pass2 <<<BH * 32, 256, smem2>>>(Q, O, D1);
}

// round 4
// speedup vs baseline: 1.3044x; 1.3044x over previous
#include <cuda_runtime.h>
#include <cstdint>

#define NEG_CLAMP -20.0f
#define EPSV 1e-6f

static constexpr int Bb = 8, Ll = 4096, Hh = 16, Ee = 64;
static constexpr int BH = Bb * Hh;         // 128
static constexpr int RS = Hh * Ee;         // 1024 floats per L-row
static constexpr int SPLIT = 8;
static constexpr int ROWS1 = Ll / SPLIT;   // 512 rows per pass-1 block
static constexpr int TILE = 64;            // rows per pipeline tile
static constexpr int NT1 = ROWS1 / TILE;   // 8
static constexpr int CH2 = 256;            // rows per pass-2 block
static constexpr int NT2 = CH2 / TILE;     // 4

// scratch (static device arrays: allowed; runtime alloc is not)
__device__ float g_kv_part[SPLIT * BH * Ee * Ee];
__device__ float g_ks_part[SPLIT * BH * Ee];
__device__ float g_kv[BH * Ee * Ee];
__device__ float g_ks[BH * Ee];

typedef unsigned long long u64;

__device__ __forceinline__ u64 pack2(float x, float y) {
    u64 r; asm("mov.b64 %0, {%1, %2};" : "=l"(r) : "f"(x), "f"(y)); return r;
}
__device__ __forceinline__ float2 unpack2(u64 v) {
    float2 r; asm("mov.b64 {%0, %1}, %2;" : "=f"(r.x), "=f"(r.y) : "l"(v)); return r;
}
// Blackwell packed fp32 FMA: 2 MACs/instr (FFMA2), 2x FFMA-3reg throughput
__device__ __forceinline__ u64 ffma2(u64 a, u64 b, u64 c) {
    u64 d; asm("fma.rn.f32x2 %0, %1, %2, %3;" : "=l"(d) : "l"(a), "l"(b), "l"(c)); return d;
}
__device__ __forceinline__ u64 fmul2(u64 a, u64 b) {
    u64 d; asm("mul.rn.f32x2 %0, %1, %2;" : "=l"(d) : "l"(a), "l"(b)); return d;
}
__device__ __forceinline__ void cpa16(uint32_t dst, const float* src) {
    asm volatile("cp.async.cg.shared.global [%0], [%1], 16;" :: "r"(dst), "l"(src));
}
#define CP_COMMIT() asm volatile("cp.async.commit_group;")
#define CP_WAIT1()  asm volatile("cp.async.wait_group 1;")
#define CP_WAIT0()  asm volatile("cp.async.wait_group 0;")

// ---------------------------------------------------------------------------
// Pass 1: per (head, L-split): KV_partial = phi(K)^T V  (64x64), ksum_partial
// cp.async double-buffered pipeline: copy(i+1) in flight during softmax+gemm(i)
// smem: kraw[2][64][64] | v[2][64][64] | phi_dup[64][128]   = 96 KB
// ---------------------------------------------------------------------------
__global__ void __launch_bounds__(256) k_pass1(const float* __restrict__ Kin,
                                               const float* __restrict__ Vin,
                                               const float* __restrict__ D1) {
    extern __shared__ __align__(16) float sm1[];
    float* s_kraw = sm1;             // 2*4096
    float* s_v    = sm1 + 8192;      // 2*4096
    float* s_phi  = sm1 + 16384;     // 8192 (dup pairs, row stride 128 floats)
    const uint32_t sb = (uint32_t)__cvta_generic_to_shared(sm1);

    const int bh = blockIdx.x / SPLIT, sp = blockIdx.x % SPLIT;
    const int b = bh >> 4, h = bh & 15;
    const int tid = threadIdx.x, w = tid >> 5, lane = tid & 31;
    const int dg = tid & 7, eg = tid >> 3;  // thread owns e-rows {2eg,2eg+1}, d {4dg..4dg+3, 32+4dg..35+4dg}
    const float invT = 1.0f / log1pf(__expf(*D1));
    const float* Kb = Kin + (long)b * Ll * RS + h * Ee + (long)sp * ROWS1 * RS;
    const float* Vb = Vin + (long)b * Ll * RS + h * Ee + (long)sp * ROWS1 * RS;

    auto issue_copy = [&](int tile) {
        const int buf = tile & 1;
        const float* ksrc = Kb + (long)tile * TILE * RS;
        const float* vsrc = Vb + (long)tile * TILE * RS;
        const uint32_t kd = sb + (uint32_t)(buf * 4096) * 4u;
        const uint32_t vd = sb + (uint32_t)(8192 + buf * 4096) * 4u;
        #pragma unroll
        for (int c = 0; c < 4; c++) {
            int lin = tid + 256 * c;
            int r = lin >> 4, q = (lin & 15) * 4;
            long off = (long)r * RS + q;
            uint32_t doff = (uint32_t)(r * 64 + q) * 4u;
            cpa16(kd + doff, ksrc + off);
            cpa16(vd + doff, vsrc + off);
        }
    };

    u64 acc[2][4];
    #pragma unroll
    for (int p = 0; p < 2; p++)
        #pragma unroll
        for (int j = 0; j < 4; j++) acc[p][j] = 0ull;
    float ks0 = 0.f, ks1 = 0.f;

    issue_copy(0); CP_COMMIT();

    for (int tile = 0; tile < NT1; tile++) {
        const int buf = tile & 1;
        if (tile + 1 < NT1) { issue_copy(tile + 1); CP_COMMIT(); CP_WAIT1(); }
        else CP_WAIT0();
        __syncthreads();

        // softmax(K rows): warp w handles rows w, w+8, ...; 2 rows/iter for SHFL ILP
        const float* kr = s_kraw + buf * 4096;
        #pragma unroll
        for (int i = 0; i < 8; i += 2) {
            const int r0 = w + 8 * i, r1 = r0 + 8;
            float a0 = kr[r0 * 64 + lane], a1 = kr[r0 * 64 + lane + 32];
            float b0 = kr[r1 * 64 + lane], b1 = kr[r1 * 64 + lane + 32];
            a0 = a0 < 0.f ? NEG_CLAMP : a0;  a1 = a1 < 0.f ? NEG_CLAMP : a1;
            b0 = b0 < 0.f ? NEG_CLAMP : b0;  b1 = b1 < 0.f ? NEG_CLAMP : b1;
            float ea0 = __expf(a0 * invT), ea1 = __expf(a1 * invT);
            float eb0 = __expf(b0 * invT), eb1 = __expf(b1 * invT);
            float sa = ea0 + ea1, sbv = eb0 + eb1;
            #pragma unroll
            for (int o = 16; o > 0; o >>= 1) {
                sa  += __shfl_xor_sync(0xffffffffu, sa,  o);
                sbv += __shfl_xor_sync(0xffffffffu, sbv, o);
            }
            float ra = 1.0f / sa, rb = 1.0f / sbv;
            ea0 *= ra; ea1 *= ra; eb0 *= rb; eb1 *= rb;
            ks0 += ea0 + eb0; ks1 += ea1 + eb1;
            *(u64*)(s_phi + r0 * 128 + lane * 2)        = pack2(ea0, ea0);
            *(u64*)(s_phi + r0 * 128 + (lane + 32) * 2) = pack2(ea1, ea1);
            *(u64*)(s_phi + r1 * 128 + lane * 2)        = pack2(eb0, eb0);
            *(u64*)(s_phi + r1 * 128 + (lane + 32) * 2) = pack2(eb1, eb1);
        }
        __syncthreads();

        // rank-1 accumulation: 3 LDS.128 + 8 FFMA2 per k-row
        const float* vt = s_v + buf * 4096;
        #pragma unroll 4
        for (int r = 0; r < TILE; r++) {
            ulonglong2 ph = *(const ulonglong2*)(s_phi + r * 128 + eg * 4);
            ulonglong2 va = *(const ulonglong2*)(vt + r * 64 + dg * 4);
            ulonglong2 vb = *(const ulonglong2*)(vt + r * 64 + 32 + dg * 4);
            acc[0][0] = ffma2(ph.x, va.x, acc[0][0]);
            acc[0][1] = ffma2(ph.x, va.y, acc[0][1]);
            acc[0][2] = ffma2(ph.x, vb.x, acc[0][2]);
            acc[0][3] = ffma2(ph.x, vb.y, acc[0][3]);
            acc[1][0] = ffma2(ph.y, va.x, acc[1][0]);
            acc[1][1] = ffma2(ph.y, va.y, acc[1][1]);
            acc[1][2] = ffma2(ph.y, vb.x, acc[1][2]);
            acc[1][3] = ffma2(ph.y, vb.y, acc[1][3]);
        }
        __syncthreads(); // before copy(tile+2) overwrites v[buf]
    }

    // write partial KV (each element owned by exactly one thread) — coalesced
    float* dst = g_kv_part + ((long)sp * BH + bh) * 4096;
    #pragma unroll
    for (int p = 0; p < 2; p++) {
        const int row = 2 * eg + p;
        float2 c0 = unpack2(acc[p][0]), c1 = unpack2(acc[p][1]);
        float2 c2 = unpack2(acc[p][2]), c3 = unpack2(acc[p][3]);
        float4 f;
        f.x = c0.x; f.y = c0.y; f.z = c1.x; f.w = c1.y;
        *(float4*)(dst + row * 64 + 4 * dg) = f;
        f.x = c2.x; f.y = c2.y; f.z = c3.x; f.w = c3.y;
        *(float4*)(dst + row * 64 + 32 + 4 * dg) = f;
    }
    // ksum partial: per-warp columns -> smem -> 64 sums (deterministic order)
    s_kraw[w * 64 + lane] = ks0;
    s_kraw[w * 64 + lane + 32] = ks1;
    __syncthreads();
    if (tid < 64) {
        float s = 0.f;
        #pragma unroll
        for (int ww = 0; ww < 8; ww++) s += s_kraw[ww * 64 + tid];
        g_ks_part[((long)sp * BH + bh) * 64 + tid] = s;
    }
}

// ---------------------------------------------------------------------------
// Deterministic split reduction (512 blocks)
// ---------------------------------------------------------------------------
__global__ void __launch_bounds__(256) k_reduce() {
    const int bh = blockIdx.x >> 2, part = blockIdx.x & 3;
    const int tid = threadIdx.x;
    const int i4 = part * 1024 + tid * 4;
    float4 s = make_float4(0.f, 0.f, 0.f, 0.f);
    #pragma unroll
    for (int sp = 0; sp < SPLIT; sp++) {
        float4 v = *(const float4*)(g_kv_part + ((long)sp * BH + bh) * 4096 + i4);
        s.x += v.x; s.y += v.y; s.z += v.z; s.w += v.w;
    }
    *(float4*)(g_kv + (long)bh * 4096 + i4) = s;
    if (part == 0 && tid < 64) {
        float t = 0.f;
        #pragma unroll
        for (int sp = 0; sp < SPLIT; sp++)
            t += g_ks_part[((long)sp * BH + bh) * 64 + tid];
        g_ks[(long)bh * 64 + tid] = t;
    }
}

// ---------------------------------------------------------------------------
// Pass 2: out_l = (phi(q_l) . KV) * z_l,  z_l = 1/(phi(q_l).ksum + eps)
// 2048 blocks, each: one head x 256 L-rows, cp.async pipelined in 64-row tiles
// smem: kv[64][64] | qraw[2][64][64] | qd_dup[64][132] | z[64] | ks[64] ~ 81.5 KB
// ---------------------------------------------------------------------------
__global__ void __launch_bounds__(256) k_pass2(const float* __restrict__ Qin,
                                               float* __restrict__ Out,
                                               const float* __restrict__ D1) {
    extern __shared__ __align__(16) float sm2[];
    float* s_kv   = sm2;              // 4096
    float* s_qraw = sm2 + 4096;       // 2*4096
    float* s_qd   = sm2 + 12288;      // 64*132 = 8448 (dup pairs, 16B-aligned rows)
    float* s_z    = sm2 + 20736;      // 64
    float* s_ks   = sm2 + 20800;      // 64  (total 20864 floats)
    const uint32_t sb = (uint32_t)__cvta_generic_to_shared(sm2);

    const int bh = blockIdx.x >> 4, chunk = blockIdx.x & 15;
    const int b = bh >> 4, h = bh & 15;
    const int tid = threadIdx.x, w = tid >> 5, lane = tid & 31;
    const int dg = tid & 7, rg = tid >> 3;  // thread owns rows {2rg,2rg+1}, d {4dg..4dg+3, 32+4dg..35+4dg}
    const float invT = 1.0f / log1pf(__expf(*D1));
    const float* Qb = Qin + (long)b * Ll * RS + h * Ee + (long)chunk * CH2 * RS;
    float*       Ob = Out + (long)b * Ll * RS + h * Ee + (long)chunk * CH2 * RS;

    auto issue_copy = [&](int tile) {
        const int buf = tile & 1;
        const float* qs = Qb + (long)tile * TILE * RS;
        const uint32_t qd_ = sb + (uint32_t)(4096 + buf * 4096) * 4u;
        #pragma unroll
        for (int c = 0; c < 4; c++) {
            int lin = tid + 256 * c;
            int r = lin >> 4, q = (lin & 15) * 4;
            cpa16(qd_ + (uint32_t)(r * 64 + q) * 4u, qs + (long)r * RS + q);
        }
    };

    issue_copy(0); CP_COMMIT();

    // stage KV + ksum (LDG latency overlaps the in-flight cp.async)
    {
        const float* kvsrc = g_kv + (long)bh * 4096;
        float4 kvr[4];
        #pragma unroll
        for (int c = 0; c < 4; c++) kvr[c] = *(const float4*)(kvsrc + (tid + 256 * c) * 4);
        float ksr = (tid < 64) ? g_ks[(long)bh * 64 + tid] : 0.f;
        #pragma unroll
        for (int c = 0; c < 4; c++) *(float4*)(s_kv + (tid + 256 * c) * 4) = kvr[c];
        if (tid < 64) s_ks[tid] = ksr;
    }

    for (int tile = 0; tile < NT2; tile++) {
        const int buf = tile & 1;
        if (tile + 1 < NT2) { issue_copy(tile + 1); CP_COMMIT(); CP_WAIT1(); }
        else CP_WAIT0();
        __syncthreads();

        // softmax(Q rows) + z, 2 rows/iter, 4 interleaved SHFL chains
        const float* qr = s_qraw + buf * 4096;
        const float ksA = s_ks[lane], ksB = s_ks[lane + 32];
        #pragma unroll
        for (int i = 0; i < 8; i += 2) {
            const int r0 = w + 8 * i, r1 = r0 + 8;
            float a0 = qr[r0 * 64 + lane], a1 = qr[r0 * 64 + lane + 32];
            float b0 = qr[r1 * 64 + lane], b1 = qr[r1 * 64 + lane + 32];
            a0 = a0 < 0.f ? NEG_CLAMP : a0;  a1 = a1 < 0.f ? NEG_CLAMP : a1;
            b0 = b0 < 0.f ? NEG_CLAMP : b0;  b1 = b1 < 0.f ? NEG_CLAMP : b1;
            float ea0 = __expf(a0 * invT), ea1 = __expf(a1 * invT);
            float eb0 = __expf(b0 * invT), eb1 = __expf(b1 * invT);
            float sa = ea0 + ea1,             sbv = eb0 + eb1;
            float da = ea0 * ksA + ea1 * ksB, db  = eb0 * ksA + eb1 * ksB;
            #pragma unroll
            for (int o = 16; o > 0; o >>= 1) {
                sa  += __shfl_xor_sync(0xffffffffu, sa,  o);
                da  += __shfl_xor_sync(0xffffffffu, da,  o);
                sbv += __shfl_xor_sync(0xffffffffu, sbv, o);
                db  += __shfl_xor_sync(0xffffffffu, db,  o);
            }
            float ra = 1.0f / sa, rb = 1.0f / sbv;
            ea0 *= ra; ea1 *= ra; eb0 *= rb; eb1 *= rb;
            *(u64*)(s_qd + lane * 132 + r0 * 2)        = pack2(ea0, ea0);
            *(u64*)(s_qd + (lane + 32) * 132 + r0 * 2) = pack2(ea1, ea1);
            *(u64*)(s_qd + lane * 132 + r1 * 2)        = pack2(eb0, eb0);
            *(u64*)(s_qd + (lane + 32) * 132 + r1 * 2) = pack2(eb1, eb1);
            if (lane == 0) {
                s_z[r0] = 1.0f / (da * ra + EPSV);
                s_z[r1] = 1.0f / (db * rb + EPSV);
            }
        }
        __syncthreads();

        // GEMM: 3 LDS.128 + 8 FFMA2 per e; then scale by z and store (coalesced)
        u64 acc[2][4];
        #pragma unroll
        for (int p = 0; p < 2; p++)
            #pragma unroll
            for (int j = 0; j < 4; j++) acc[p][j] = 0ull;
        #pragma unroll 4
        for (int e = 0; e < 64; e++) {
            ulonglong2 qq = *(const ulonglong2*)(s_qd + e * 132 + rg * 4);
            ulonglong2 ka = *(const ulonglong2*)(s_kv + e * 64 + dg * 4);
            ulonglong2 kb = *(const ulonglong2*)(s_kv + e * 64 + 32 + dg * 4);
            acc[0][0] = ffma2(qq.x, ka.x, acc[0][0]);
            acc[0][1] = ffma2(qq.x, ka.y, acc[0][1]);
            acc[0][2] = ffma2(qq.x, kb.x, acc[0][2]);
            acc[0][3] = ffma2(qq.x, kb.y, acc[0][3]);
            acc[1][0] = ffma2(qq.y, ka.x, acc[1][0]);
            acc[1][1] = ffma2(qq.y, ka.y, acc[1][1]);
            acc[1][2] = ffma2(qq.y, kb.x, acc[1][2]);
            acc[1][3] = ffma2(qq.y, kb.y, acc[1][3]);
        }
        const u64 zp0 = pack2(s_z[2 * rg], s_z[2 * rg]);
        const u64 zp1 = pack2(s_z[2 * rg + 1], s_z[2 * rg + 1]);
        #pragma unroll
        for (int p = 0; p < 2; p++) {
            const u64 zp = p ? zp1 : zp0;
            float2 c0 = unpack2(fmul2(acc[p][0], zp)), c1 = unpack2(fmul2(acc[p][1], zp));
            float2 c2 = unpack2(fmul2(acc[p][2], zp)), c3 = unpack2(fmul2(acc[p][3], zp));
            float* o = Ob + (long)(tile * TILE + 2 * rg + p) * RS;
            float4 f;
            f.x = c0.x; f.y = c0.y; f.z = c1.x; f.w = c1.y;
            *(float4*)(o + 4 * dg) = f;
            f.x = c2.x; f.y = c2.y; f.z = c3.x; f.w = c3.y;
            *(float4*)(o + 32 + 4 * dg) = f;
        }
        // no trailing sync needed: next softmax write to s_qd/s_z is fenced by
        // next iteration's post-wait __syncthreads; copies touch only s_qraw.
    }
}

extern "C" void kernel_launch(void* const* d_in, const int* in_sizes, int n_in,
                              void* d_out, int out_size) {
    const float* Q  = (const float*)d_in[0];
    const float* K  = (const float*)d_in[1];
    const float* V  = (const float*)d_in[2];
    const float* D1 = (const float*)d_in[3];
    float* O = (float*)d_out;

    const int smem1 = 24576 * 4;  // 98304 B
    const int smem2 = 20864 * 4;  // 83456 B
    cudaFuncSetAttribute(k_pass1, cudaFuncAttributeMaxDynamicSharedMemorySize, smem1);
    cudaFuncSetAttribute(k_pass2, cudaFuncAttributeMaxDynamicSharedMemorySize, smem2);

    k_pass1 <<<BH * SPLIT, 256, smem1>>>(K, V, D1);
    k_reduce<<<BH * 4, 256>>>();
    k_pass2 <<<BH * 16, 256, smem2>>>(Q, O, D1);
}

// round 6
// speedup vs baseline: 1.3332x; 1.0221x over previous
#include <cuda_runtime.h>
#include <cstdint>

#define NEG_CLAMP -20.0f
#define EPSV 1e-6f

static constexpr int Bb = 8, Ll = 4096, Hh = 16, Ee = 64;
static constexpr int BH = Bb * Hh;         // 128
static constexpr int RS = Hh * Ee;         // 1024 floats per L-row
static constexpr int SPLIT = 8;
static constexpr int ROWS1 = Ll / SPLIT;   // 512 rows per pass-1 block
static constexpr int TILE = 64;            // rows per pipeline tile
static constexpr int NT1 = ROWS1 / TILE;   // 8
static constexpr int CH2 = 128;            // rows per pass-2 block
static constexpr int NT2 = CH2 / TILE;     // 2

__device__ float g_kv_part[SPLIT * BH * Ee * Ee];
__device__ float g_ks_part[SPLIT * BH * Ee];
__device__ float g_kv[BH * Ee * Ee];
__device__ float g_ks[BH * Ee];

typedef unsigned long long u64;

__device__ __forceinline__ u64 pack2(float x, float y) {
    u64 r; asm("mov.b64 %0, {%1, %2};" : "=l"(r) : "f"(x), "f"(y)); return r;
}
__device__ __forceinline__ float2 unpack2(u64 v) {
    float2 r; asm("mov.b64 {%0, %1}, %2;" : "=f"(r.x), "=f"(r.y) : "l"(v)); return r;
}
__device__ __forceinline__ u64 ffma2(u64 a, u64 b, u64 c) {
    u64 d; asm("fma.rn.f32x2 %0, %1, %2, %3;" : "=l"(d) : "l"(a), "l"(b), "l"(c)); return d;
}
__device__ __forceinline__ u64 fmul2(u64 a, u64 b) {
    u64 d; asm("mul.rn.f32x2 %0, %1, %2;" : "=l"(d) : "l"(a), "l"(b)); return d;
}
__device__ __forceinline__ void cpa16(uint32_t dst, const float* src) {
    asm volatile("cp.async.cg.shared.global [%0], [%1], 16;" :: "r"(dst), "l"(src));
}
#define CP_COMMIT() asm volatile("cp.async.commit_group;")
#define CP_WAIT1()  asm volatile("cp.async.wait_group 1;")
#define CP_WAIT0()  asm volatile("cp.async.wait_group 0;")

// Dup-row layout (128 floats = 32 x 16B chunks). Chunk u -> slot (u&3)*8 + (u>>2)
// (bijection on 0..31). Inverse: slot s = 8c + g holds chunk 4g + c, so a GEMM
// thread with group index g issues instr c at float offset 32c + 4g and gets
// pairs (8g+2c, 8g+2c+1). Per instr the warp hits 4 or 8 distinct 16B words,
// 128B-contiguous -> conflict-free broadcast.
__device__ __forceinline__ int doff(int e) {   // float offset of dup pair e
    int u = e >> 1;
    return (((u & 3) << 3) + (u >> 2)) * 4 + (e & 1) * 2;
}
// Natural 64-float rows (16 chunks): chunk k -> slot (k>>1) + (k&1)*8 (bijection).
// Thread dg wants chunks {2dg, 2dg+1} -> slots {dg, dg+8} -> floats {4dg, 32+4dg}.
__device__ __forceinline__ int pvslot(int k) { return (k >> 1) + ((k & 1) << 3); }

// ---------------------------------------------------------------------------
// Pass 1: KV_partial = phi(K)^T V (64x64) per (head, L-split) + ksum_partial
// 256 threads: 4 contraction groups x 64 threads, each thread an 8x8 tile.
// smem: kraw[2][64][64] | v[2][64][64](perm pv) | phid[64][128](dup,perm) = 96KB
// ---------------------------------------------------------------------------
__global__ void __launch_bounds__(256, 2) k_pass1(const float* __restrict__ Kin,
                                                  const float* __restrict__ Vin,
                                                  const float* __restrict__ D1) {
    extern __shared__ __align__(16) float sm1[];
    float* s_kraw = sm1;            // 2*4096
    float* s_v    = sm1 + 8192;     // 2*4096 (perm pv)
    float* s_phid = sm1 + 16384;    // 64*128 (dup pairs, perm)
    const uint32_t sb = (uint32_t)__cvta_generic_to_shared(sm1);

    const int bh = blockIdx.x / SPLIT, sp = blockIdx.x % SPLIT;
    const int b = bh >> 4, h = bh & 15;
    const int tid = threadIdx.x, w = tid >> 5, lane = tid & 31;
    const int rgp = tid >> 6;                    // contraction group 0..3
    const int t = tid & 63, eg = t >> 3, dg = t & 7;
    const float invT = 1.0f / log1pf(__expf(*D1));
    const float* Kb = Kin + (long)b * Ll * RS + h * Ee + (long)sp * ROWS1 * RS;
    const float* Vb = Vin + (long)b * Ll * RS + h * Ee + (long)sp * ROWS1 * RS;
    const int dofA = doff(lane), dofB = doff(lane + 32);

    auto issue_copy = [&](int tile) {
        const int buf = tile & 1;
        const float* ksrc = Kb + (long)tile * TILE * RS;
        const float* vsrc = Vb + (long)tile * TILE * RS;
        const uint32_t kd = sb + (uint32_t)(buf * 4096) * 4u;
        const uint32_t vd = sb + (uint32_t)(8192 + buf * 4096) * 4u;
        #pragma unroll
        for (int c = 0; c < 4; c++) {
            int lin = tid + 256 * c;
            int r = lin >> 4, k = lin & 15;
            long off = (long)r * RS + k * 4;
            cpa16(kd + (uint32_t)(r * 64 + k * 4) * 4u, ksrc + off);
            cpa16(vd + (uint32_t)(r * 64 + pvslot(k) * 4) * 4u, vsrc + off);
        }
    };

    u64 acc[8][4]; // e-offset i (e=8eg+i) x d-pair j (d=8dg+2j,+1)
    #pragma unroll
    for (int i = 0; i < 8; i++)
        #pragma unroll
        for (int j = 0; j < 4; j++) acc[i][j] = 0ull;
    float ks0 = 0.f, ks1 = 0.f;

    issue_copy(0); CP_COMMIT();

    for (int tile = 0; tile < NT1; tile++) {
        const int buf = tile & 1;
        if (tile + 1 < NT1) { issue_copy(tile + 1); CP_COMMIT(); CP_WAIT1(); }
        else CP_WAIT0();
        __syncthreads();

        // softmax(K rows): warp w -> rows w+8i; 2 rows/iter for SHFL ILP
        const float* kr = s_kraw + buf * 4096;
        #pragma unroll
        for (int i = 0; i < 8; i += 2) {
            const int r0 = w + 8 * i, r1 = r0 + 8;
            float a0 = kr[r0 * 64 + lane], a1 = kr[r0 * 64 + lane + 32];
            float b0 = kr[r1 * 64 + lane], b1 = kr[r1 * 64 + lane + 32];
            a0 = a0 < 0.f ? NEG_CLAMP : a0;  a1 = a1 < 0.f ? NEG_CLAMP : a1;
            b0 = b0 < 0.f ? NEG_CLAMP : b0;  b1 = b1 < 0.f ? NEG_CLAMP : b1;
            float ea0 = __expf(a0 * invT), ea1 = __expf(a1 * invT);
            float eb0 = __expf(b0 * invT), eb1 = __expf(b1 * invT);
            float sa = ea0 + ea1, sbv = eb0 + eb1;
            #pragma unroll
            for (int o = 16; o > 0; o >>= 1) {
                sa  += __shfl_xor_sync(0xffffffffu, sa,  o);
                sbv += __shfl_xor_sync(0xffffffffu, sbv, o);
            }
            float ra = 1.0f / sa, rb = 1.0f / sbv;
            ea0 *= ra; ea1 *= ra; eb0 *= rb; eb1 *= rb;
            ks0 += ea0 + eb0; ks1 += ea1 + eb1;
            *(u64*)(s_phid + r0 * 128 + dofA) = pack2(ea0, ea0);
            *(u64*)(s_phid + r0 * 128 + dofB) = pack2(ea1, ea1);
            *(u64*)(s_phid + r1 * 128 + dofA) = pack2(eb0, eb0);
            *(u64*)(s_phid + r1 * 128 + dofB) = pack2(eb1, eb1);
        }
        __syncthreads();

        // GEMM: group rgp handles rows 16rgp..16rgp+15. Per row:
        // 4 LDS.128 phi-dup (slots 8c+eg -> floats 32c+4eg) + 2 LDS.128 v + 32 FFMA2
        const float* vt = s_v + buf * 4096;
        const float* pb = s_phid + (rgp * 16) * 128;
        #pragma unroll 2
        for (int rr = 0; rr < 16; rr++) {
            const float* pr = pb + rr * 128;
            ulonglong2 c0 = *(const ulonglong2*)(pr + 4 * eg);        // pairs 8eg+0,1
            ulonglong2 c1 = *(const ulonglong2*)(pr + 32 + 4 * eg);   // pairs 8eg+2,3
            ulonglong2 c2 = *(const ulonglong2*)(pr + 64 + 4 * eg);   // pairs 8eg+4,5
            ulonglong2 c3 = *(const ulonglong2*)(pr + 96 + 4 * eg);   // pairs 8eg+6,7
            u64 pe[8] = {c0.x, c0.y, c1.x, c1.y, c2.x, c2.y, c3.x, c3.y};
            const float* vr = vt + (rgp * 16 + rr) * 64;
            ulonglong2 v0 = *(const ulonglong2*)(vr + 4 * dg);        // d 8dg..8dg+3
            ulonglong2 v1 = *(const ulonglong2*)(vr + 32 + 4 * dg);   // d 8dg+4..+7
            u64 vv[4] = {v0.x, v0.y, v1.x, v1.y};
            #pragma unroll
            for (int i = 0; i < 8; i++)
                #pragma unroll
                for (int j = 0; j < 4; j++)
                    acc[i][j] = ffma2(pe[i], vv[j], acc[i][j]);
        }
        __syncthreads();
    }

    // deterministic contraction-group reduction via smem (once per block)
    {
        float* part = sm1 + rgp * 4096; // reuse kraw+v area (4 x 16KB)
        #pragma unroll
        for (int i = 0; i < 8; i++) {
            float2 a0 = unpack2(acc[i][0]), a1 = unpack2(acc[i][1]);
            float2 a2 = unpack2(acc[i][2]), a3 = unpack2(acc[i][3]);
            float4 f;
            float* p = part + (8 * eg + i) * 64 + 8 * dg;
            f.x = a0.x; f.y = a0.y; f.z = a1.x; f.w = a1.y; *(float4*)(p)     = f;
            f.x = a2.x; f.y = a2.y; f.z = a3.x; f.w = a3.y; *(float4*)(p + 4) = f;
        }
        // ksum partials into s_phid (phi data dead now)
        s_phid[w * 64 + lane] = ks0;
        s_phid[w * 64 + lane + 32] = ks1;
        __syncthreads();

        float* dst = g_kv_part + ((long)sp * BH + bh) * 4096;
        #pragma unroll
        for (int c = 0; c < 4; c++) {
            int off = tid * 16 + c * 4;
            float4 s = *(const float4*)(sm1 + off);
            #pragma unroll
            for (int g = 1; g < 4; g++) {
                float4 v = *(const float4*)(sm1 + g * 4096 + off);
                s.x += v.x; s.y += v.y; s.z += v.z; s.w += v.w;
            }
            *(float4*)(dst + off) = s;
        }
        if (tid < 64) {
            float s = 0.f;
            #pragma unroll
            for (int ww = 0; ww < 8; ww++) s += s_phid[ww * 64 + tid];
            g_ks_part[((long)sp * BH + bh) * 64 + tid] = s;
        }
    }
}

// ---------------------------------------------------------------------------
// Deterministic split reduction (512 blocks)
// ---------------------------------------------------------------------------
__global__ void __launch_bounds__(256) k_reduce() {
    const int bh = blockIdx.x >> 2, part = blockIdx.x & 3;
    const int tid = threadIdx.x;
    const int i4 = part * 1024 + tid * 4;
    float4 s = make_float4(0.f, 0.f, 0.f, 0.f);
    #pragma unroll
    for (int sp = 0; sp < SPLIT; sp++) {
        float4 v = *(const float4*)(g_kv_part + ((long)sp * BH + bh) * 4096 + i4);
        s.x += v.x; s.y += v.y; s.z += v.z; s.w += v.w;
    }
    *(float4*)(g_kv + (long)bh * 4096 + i4) = s;
    if (part == 0 && tid < 64) {
        float t = 0.f;
        #pragma unroll
        for (int sp = 0; sp < SPLIT; sp++)
            t += g_ks_part[((long)sp * BH + bh) * 64 + tid];
        g_ks[(long)bh * 64 + tid] = t;
    }
}

// ---------------------------------------------------------------------------
// Pass 2: out_l = (phi(q_l) . KV) * z_l. 4096 blocks, one head x 128 rows.
// f32x2 lanes = row pairs: acc = (out[r][d], out[r+1][d]); q row-pairs via
// LDS.64 from transposed qT; KV pre-duplicated (perm) in smem.
// smem: kvd[64][128] | qraw[2][64][64] | qT[64][130] | z[128] | ks[64] ~ 97KB
// ---------------------------------------------------------------------------
__global__ void __launch_bounds__(256, 2) k_pass2(const float* __restrict__ Qin,
                                                  float* __restrict__ Out,
                                                  const float* __restrict__ D1) {
    extern __shared__ __align__(16) float sm2[];
    float* s_kvd  = sm2;              // 8192 (dup pairs, perm, row stride 128)
    float* s_qraw = sm2 + 8192;       // 2*4096
    float* s_qT   = sm2 + 16384;      // 64*130 = 8320, [e][r], stride 130
    float* s_z    = sm2 + 24704;      // 128
    float* s_ks   = sm2 + 24832;      // 64   (total 24896 floats)
    const uint32_t sb = (uint32_t)__cvta_generic_to_shared(sm2);

    const int bh = blockIdx.x >> 5, chunk = blockIdx.x & 31;
    const int b = bh >> 4, h = bh & 15;
    const int tid = threadIdx.x, w = tid >> 5, lane = tid & 31;
    const int rg = tid >> 3, dg = tid & 7;   // rows 4rg..4rg+3, d 8dg..8dg+7
    const float invT = 1.0f / log1pf(__expf(*D1));
    const float* Qb = Qin + (long)b * Ll * RS + h * Ee + (long)chunk * CH2 * RS;
    float*       Ob = Out + (long)b * Ll * RS + h * Ee + (long)chunk * CH2 * RS;

    auto issue_copy = [&](int tile) {
        const int buf = tile & 1;
        const float* qs = Qb + (long)tile * TILE * RS;
        const uint32_t qd = sb + (uint32_t)(8192 + buf * 4096) * 4u;
        #pragma unroll
        for (int c = 0; c < 4; c++) {
            int lin = tid + 256 * c;
            int r = lin >> 4, k = lin & 15;
            cpa16(qd + (uint32_t)(r * 64 + k * 4) * 4u, qs + (long)r * RS + k * 4);
        }
    };

    issue_copy(0); CP_COMMIT();
    issue_copy(1); CP_COMMIT();

    // stage KV duplicated+permuted, and ksum (overlaps in-flight cp.async)
    {
        const float* kvsrc = g_kv + (long)bh * 4096;
        #pragma unroll
        for (int c = 0; c < 4; c++) {
            int i4 = tid + 256 * c;
            float4 v4 = *(const float4*)(kvsrc + i4 * 4);
            int e = i4 >> 4, d0 = (i4 & 15) * 4;
            float* rowb = s_kvd + e * 128;
            *(u64*)(rowb + doff(d0 + 0)) = pack2(v4.x, v4.x);
            *(u64*)(rowb + doff(d0 + 1)) = pack2(v4.y, v4.y);
            *(u64*)(rowb + doff(d0 + 2)) = pack2(v4.z, v4.z);
            *(u64*)(rowb + doff(d0 + 3)) = pack2(v4.w, v4.w);
        }
        if (tid < 64) s_ks[tid] = g_ks[(long)bh * 64 + tid];
    }

    // softmax both tiles into transposed qT + z
    #pragma unroll
    for (int tile = 0; tile < NT2; tile++) {
        if (tile == 0) CP_WAIT1(); else CP_WAIT0();
        __syncthreads();
        const float* qr = s_qraw + tile * 4096;
        const float ksA = s_ks[lane], ksB = s_ks[lane + 32];
        const int rbase = tile * TILE;
        #pragma unroll
        for (int i = 0; i < 8; i += 2) {
            const int r0 = w + 8 * i, r1 = r0 + 8;
            float a0 = qr[r0 * 64 + lane], a1 = qr[r0 * 64 + lane + 32];
            float b0 = qr[r1 * 64 + lane], b1 = qr[r1 * 64 + lane + 32];
            a0 = a0 < 0.f ? NEG_CLAMP : a0;  a1 = a1 < 0.f ? NEG_CLAMP : a1;
            b0 = b0 < 0.f ? NEG_CLAMP : b0;  b1 = b1 < 0.f ? NEG_CLAMP : b1;
            float ea0 = __expf(a0 * invT), ea1 = __expf(a1 * invT);
            float eb0 = __expf(b0 * invT), eb1 = __expf(b1 * invT);
            float sa = ea0 + ea1,             sbv = eb0 + eb1;
            float da = ea0 * ksA + ea1 * ksB, db  = eb0 * ksA + eb1 * ksB;
            #pragma unroll
            for (int o = 16; o > 0; o >>= 1) {
                sa  += __shfl_xor_sync(0xffffffffu, sa,  o);
                da  += __shfl_xor_sync(0xffffffffu, da,  o);
                sbv += __shfl_xor_sync(0xffffffffu, sbv, o);
                db  += __shfl_xor_sync(0xffffffffu, db,  o);
            }
            float ra = 1.0f / sa, rb = 1.0f / sbv;
            ea0 *= ra; ea1 *= ra; eb0 *= rb; eb1 *= rb;
            s_qT[lane * 130 + rbase + r0]        = ea0;
            s_qT[(lane + 32) * 130 + rbase + r0] = ea1;
            s_qT[lane * 130 + rbase + r1]        = eb0;
            s_qT[(lane + 32) * 130 + rbase + r1] = eb1;
            if (lane == 0) {
                s_z[rbase + r0] = 1.0f / (da * ra + EPSV);
                s_z[rbase + r1] = 1.0f / (db * rb + EPSV);
            }
        }
    }
    __syncthreads();

    // GEMM over 128 rows: per e: 2 LDS.64 (q row-pairs, broadcast)
    // + 4 LDS.128 (kv-dup at floats 32c+4dg) + 16 FFMA2
    u64 acc[2][8];
    #pragma unroll
    for (int p = 0; p < 2; p++)
        #pragma unroll
        for (int j = 0; j < 8; j++) acc[p][j] = 0ull;

    #pragma unroll 2
    for (int e = 0; e < 64; e++) {
        const float* qc = s_qT + e * 130 + 4 * rg;
        u64 q0 = *(const u64*)(qc);       // rows 4rg, 4rg+1
        u64 q1 = *(const u64*)(qc + 2);   // rows 4rg+2, 4rg+3
        const float* kr = s_kvd + e * 128;
        ulonglong2 k0 = *(const ulonglong2*)(kr + 4 * dg);        // d 8dg+0,1
        ulonglong2 k1 = *(const ulonglong2*)(kr + 32 + 4 * dg);   // d 8dg+2,3
        ulonglong2 k2 = *(const ulonglong2*)(kr + 64 + 4 * dg);   // d 8dg+4,5
        ulonglong2 k3 = *(const ulonglong2*)(kr + 96 + 4 * dg);   // d 8dg+6,7
        u64 kd[8] = {k0.x, k0.y, k1.x, k1.y, k2.x, k2.y, k3.x, k3.y};
        #pragma unroll
        for (int j = 0; j < 8; j++) {
            acc[0][j] = ffma2(q0, kd[j], acc[0][j]);
            acc[1][j] = ffma2(q1, kd[j], acc[1][j]);
        }
    }

    // scale by z (packed per row-pair) and store 4 rows x 8 d
    #pragma unroll
    for (int p = 0; p < 2; p++) {
        const int r0 = 4 * rg + 2 * p;
        const u64 zp = pack2(s_z[r0], s_z[r0 + 1]);
        float2 sc[8];
        #pragma unroll
        for (int j = 0; j < 8; j++) sc[j] = unpack2(fmul2(acc[p][j], zp));
        float* oA = Ob + (long)r0 * RS + 8 * dg;
        float4 f;
        f.x = sc[0].x; f.y = sc[1].x; f.z = sc[2].x; f.w = sc[3].x; *(float4*)(oA)     = f;
        f.x = sc[4].x; f.y = sc[5].x; f.z = sc[6].x; f.w = sc[7].x; *(float4*)(oA + 4) = f;
        float* oB = oA + RS;
        f.x = sc[0].y; f.y = sc[1].y; f.z = sc[2].y; f.w = sc[3].y; *(float4*)(oB)     = f;
        f.x = sc[4].y; f.y = sc[5].y; f.z = sc[6].y; f.w = sc[7].y; *(float4*)(oB + 4) = f;
    }
}

extern "C" void kernel_launch(void* const* d_in, const int* in_sizes, int n_in,
                              void* d_out, int out_size) {
    const float* Q  = (const float*)d_in[0];
    const float* K  = (const float*)d_in[1];
    const float* V  = (const float*)d_in[2];
    const float* D1 = (const float*)d_in[3];
    float* O = (float*)d_out;

    const int smem1 = 24576 * 4;  // 98304 B
    const int smem2 = 24896 * 4;  // 99584 B
    cudaFuncSetAttribute(k_pass1, cudaFuncAttributeMaxDynamicSharedMemorySize, smem1);
    cudaFuncSetAttribute(k_pass2, cudaFuncAttributeMaxDynamicSharedMemorySize, smem2);

    k_pass1 <<<BH * SPLIT, 256, smem1>>>(K, V, D1);
    k_reduce<<<BH * 4, 256>>>();
    k_pass2 <<<BH * 32, 256, smem2>>>(Q, O, D1);
}

// round 7
// speedup vs baseline: 1.4604x; 1.0955x over previous
#include <cuda_runtime.h>
#include <cstdint>

#define NEG_CLAMP -20.0f
#define EPSV 1e-6f

static constexpr int Bb = 8, Ll = 4096, Hh = 16, Ee = 64;
static constexpr int BH = Bb * Hh;         // 128
static constexpr int RS = Hh * Ee;         // 1024 floats per L-row
static constexpr int SPLIT = 8;
static constexpr int ROWS1 = Ll / SPLIT;   // 512 rows per pass-1 block
static constexpr int TILE = 64;            // pass-1 tile rows
static constexpr int NT1 = ROWS1 / TILE;   // 8 windows
static constexpr int CH2 = 512;            // pass-2 rows per block
static constexpr int T2 = 128;             // pass-2 tile rows
static constexpr int NT2 = CH2 / T2;       // 4 windows

__device__ float g_kv_part[SPLIT * BH * Ee * Ee];
__device__ float g_ks_part[SPLIT * BH * Ee];
__device__ float g_kv[BH * Ee * Ee];
__device__ float g_ks[BH * Ee];

typedef unsigned long long u64;

__device__ __forceinline__ u64 pack2(float x, float y) {
    u64 r; asm("mov.b64 %0, {%1, %2};" : "=l"(r) : "f"(x), "f"(y)); return r;
}
__device__ __forceinline__ float2 unpack2(u64 v) {
    float2 r; asm("mov.b64 {%0, %1}, %2;" : "=f"(r.x), "=f"(r.y) : "l"(v)); return r;
}
__device__ __forceinline__ u64 ffma2(u64 a, u64 b, u64 c) {
    u64 d; asm("fma.rn.f32x2 %0, %1, %2, %3;" : "=l"(d) : "l"(a), "l"(b), "l"(c)); return d;
}
__device__ __forceinline__ u64 fmul2(u64 a, u64 b) {
    u64 d; asm("mul.rn.f32x2 %0, %1, %2;" : "=l"(d) : "l"(a), "l"(b)); return d;
}
__device__ __forceinline__ void cpa16(uint32_t dst, const float* src) {
    asm volatile("cp.async.cg.shared.global [%0], [%1], 16;" :: "r"(dst), "l"(src));
}
#define CP_COMMIT() asm volatile("cp.async.commit_group;")
#define CP_WAIT2()  asm volatile("cp.async.wait_group 2;")

// 64-float rows (16 chunks): chunk k -> slot (k>>1) + (k&1)*8 (bijection).
// Reader thread g: chunks {2g,2g+1} -> slots {g, g+8} -> floats {4g, 32+4g}.
__device__ __forceinline__ int pvslot(int k) { return (k >> 1) + ((k & 1) << 3); }
// Dup-row layout (128 floats = 32 chunks): chunk u -> slot (u&3)*8 + (u>>2).
// Reader instr c at float 32c+4g -> slot 8c+g -> chunk 4g+c -> d pairs (8g+2c, +1).
__device__ __forceinline__ int doff(int e) {   // float offset of dup pair e
    int u = e >> 1;
    return (((u & 3) << 3) + (u >> 2)) * 4 + (e & 1) * 2;
}

// ---------------------------------------------------------------------------
// Pass 1: KV_partial = phi(K)^T V per (head, L-split) + ksum_partial.
// Pipelined windows: anti-phase warps overlap softmax(t+1) with GEMM(t).
// smem floats: v[3][64*64] (perm) = 12288 | phi[2][64*68] = 8704 -> 83968 B
// ---------------------------------------------------------------------------
__global__ void __launch_bounds__(256, 2) k_pass1(const float* __restrict__ Kin,
                                                  const float* __restrict__ Vin,
                                                  const float* __restrict__ D1) {
    extern __shared__ __align__(16) float sm1[];
    float* s_v   = sm1;             // 3 x 4096
    float* s_phi = sm1 + 12288;     // 2 x 4352 (rows stride 68, perm pv)
    const uint32_t sb = (uint32_t)__cvta_generic_to_shared(sm1);

    const int bh = blockIdx.x / SPLIT, sp = blockIdx.x % SPLIT;
    const int b = bh >> 4, h = bh & 15;
    const int tid = threadIdx.x, w = tid >> 5, lane = tid & 31;
    const int sub = lane >> 3, p = lane & 7;          // softmax: 8 lanes per row
    const int rgp = tid >> 6;                         // GEMM contraction group
    const int t64 = tid & 63, eg = t64 >> 3, dg = t64 & 7;
    const float invT = 1.0f / log1pf(__expf(*D1));
    const float* Kb = Kin + (long)b * Ll * RS + h * Ee + (long)sp * ROWS1 * RS;
    const float* Vb = Vin + (long)b * Ll * RS + h * Ee + (long)sp * ROWS1 * RS;

    u64 acc[8][4];
    #pragma unroll
    for (int i = 0; i < 8; i++)
        #pragma unroll
        for (int j = 0; j < 4; j++) acc[i][j] = 0ull;
    float ksl[8];
    #pragma unroll
    for (int j = 0; j < 8; j++) ksl[j] = 0.f;

    auto cp_v = [&](int tile) {
        if (tile < NT1) {
            const float* vsrc = Vb + (long)tile * TILE * RS;
            const uint32_t vd = sb + (uint32_t)((tile % 3) * 4096) * 4u;
            #pragma unroll
            for (int c = 0; c < 4; c++) {
                int lin = tid + 256 * c;
                int r = lin >> 4, k = lin & 15;
                cpa16(vd + (uint32_t)(r * 64 + pvslot(k) * 4) * 4u,
                      vsrc + (long)r * RS + k * 4);
            }
        }
        CP_COMMIT();
    };

    auto softmax1 = [&](int tile) {
        const float* ksrc = Kb + (long)tile * TILE * RS;
        float* phib = s_phi + (tile & 1) * 4352;
        #pragma unroll
        for (int it = 0; it < 2; it++) {
            const int r = w * 8 + it * 4 + sub;
            const float* kp = ksrc + (long)r * RS + 8 * p;
            float4 A = *(const float4*)kp;
            float4 B = *(const float4*)(kp + 4);
            float e0 = __expf((A.x < 0.f ? NEG_CLAMP : A.x) * invT);
            float e1 = __expf((A.y < 0.f ? NEG_CLAMP : A.y) * invT);
            float e2 = __expf((A.z < 0.f ? NEG_CLAMP : A.z) * invT);
            float e3 = __expf((A.w < 0.f ? NEG_CLAMP : A.w) * invT);
            float e4 = __expf((B.x < 0.f ? NEG_CLAMP : B.x) * invT);
            float e5 = __expf((B.y < 0.f ? NEG_CLAMP : B.y) * invT);
            float e6 = __expf((B.z < 0.f ? NEG_CLAMP : B.z) * invT);
            float e7 = __expf((B.w < 0.f ? NEG_CLAMP : B.w) * invT);
            float ls = ((e0 + e1) + (e2 + e3)) + ((e4 + e5) + (e6 + e7));
            ls += __shfl_xor_sync(0xffffffffu, ls, 1);
            ls += __shfl_xor_sync(0xffffffffu, ls, 2);
            ls += __shfl_xor_sync(0xffffffffu, ls, 4);
            float rs = 1.0f / ls;
            e0 *= rs; e1 *= rs; e2 *= rs; e3 *= rs;
            e4 *= rs; e5 *= rs; e6 *= rs; e7 *= rs;
            ksl[0] += e0; ksl[1] += e1; ksl[2] += e2; ksl[3] += e3;
            ksl[4] += e4; ksl[5] += e5; ksl[6] += e6; ksl[7] += e7;
            *(float4*)(phib + r * 68 + 4 * p)      = make_float4(e0, e1, e2, e3);
            *(float4*)(phib + r * 68 + 32 + 4 * p) = make_float4(e4, e5, e6, e7);
        }
    };

    auto gemm1 = [&](int tile) {
        const float* vt = s_v + (tile % 3) * 4096;
        const float* pb = s_phi + (tile & 1) * 4352 + rgp * 16 * 68;
        #pragma unroll 2
        for (int rr = 0; rr < 16; rr++) {
            const float* pr = pb + rr * 68;
            float4 c0 = *(const float4*)(pr + 4 * eg);       // cols 8eg..8eg+3
            float4 c1 = *(const float4*)(pr + 32 + 4 * eg);  // cols 8eg+4..+7
            u64 pe[8] = {pack2(c0.x, c0.x), pack2(c0.y, c0.y),
                         pack2(c0.z, c0.z), pack2(c0.w, c0.w),
                         pack2(c1.x, c1.x), pack2(c1.y, c1.y),
                         pack2(c1.z, c1.z), pack2(c1.w, c1.w)};
            const float* vr = vt + (rgp * 16 + rr) * 64;
            ulonglong2 v0 = *(const ulonglong2*)(vr + 4 * dg);       // d 8dg..+3
            ulonglong2 v1 = *(const ulonglong2*)(vr + 32 + 4 * dg);  // d 8dg+4..+7
            u64 vv[4] = {v0.x, v0.y, v1.x, v1.y};
            #pragma unroll
            for (int i = 0; i < 8; i++)
                #pragma unroll
                for (int j = 0; j < 4; j++)
                    acc[i][j] = ffma2(pe[i], vv[j], acc[i][j]);
        }
    };

    cp_v(0);
    cp_v(1);
    softmax1(0);
    __syncthreads();

    for (int t = 0; t < NT1; t++) {
        cp_v(t + 2);
        CP_WAIT2();              // v[t] resident
        if (w & 1) {
            gemm1(t);
            if (t + 1 < NT1) softmax1(t + 1);
        } else {
            if (t + 1 < NT1) softmax1(t + 1);
            gemm1(t);
        }
        __syncthreads();
    }

    // epilogue: deterministic contraction-group reduction + ksum staging
    {
        float* part = sm1 + rgp * 4096;            // 4 x 16KB scratch (v+phi dead)
        #pragma unroll
        for (int i = 0; i < 8; i++) {
            float2 a0 = unpack2(acc[i][0]), a1 = unpack2(acc[i][1]);
            float2 a2 = unpack2(acc[i][2]), a3 = unpack2(acc[i][3]);
            float* q = part + (8 * eg + i) * 64 + 8 * dg;
            *(float4*)(q)     = make_float4(a0.x, a0.y, a1.x, a1.y);
            *(float4*)(q + 4) = make_float4(a2.x, a2.y, a3.x, a3.y);
        }
        float* kst = sm1 + 16384;                  // 32 x 64 staging
        float* kr = kst + (w * 4 + sub) * 64 + 8 * p;
        *(float4*)(kr)     = make_float4(ksl[0], ksl[1], ksl[2], ksl[3]);
        *(float4*)(kr + 4) = make_float4(ksl[4], ksl[5], ksl[6], ksl[7]);
        __syncthreads();

        float* dst = g_kv_part + ((long)sp * BH + bh) * 4096;
        #pragma unroll
        for (int c = 0; c < 4; c++) {
            int off = tid * 16 + c * 4;
            float4 s = *(const float4*)(sm1 + off);
            #pragma unroll
            for (int g = 1; g < 4; g++) {
                float4 v = *(const float4*)(sm1 + g * 4096 + off);
                s.x += v.x; s.y += v.y; s.z += v.z; s.w += v.w;
            }
            *(float4*)(dst + off) = s;
        }
        if (tid < 64) {
            float s = 0.f;
            #pragma unroll
            for (int i = 0; i < 32; i++) s += kst[i * 64 + tid];
            g_ks_part[((long)sp * BH + bh) * 64 + tid] = s;
        }
    }
}

// ---------------------------------------------------------------------------
// Deterministic split reduction (512 blocks)
// ---------------------------------------------------------------------------
__global__ void __launch_bounds__(256) k_reduce() {
    const int bh = blockIdx.x >> 2, part = blockIdx.x & 3;
    const int tid = threadIdx.x;
    const int i4 = part * 1024 + tid * 4;
    float4 s = make_float4(0.f, 0.f, 0.f, 0.f);
    #pragma unroll
    for (int sp = 0; sp < SPLIT; sp++) {
        float4 v = *(const float4*)(g_kv_part + ((long)sp * BH + bh) * 4096 + i4);
        s.x += v.x; s.y += v.y; s.z += v.z; s.w += v.w;
    }
    *(float4*)(g_kv + (long)bh * 4096 + i4) = s;
    if (part == 0 && tid < 64) {
        float t = 0.f;
        #pragma unroll
        for (int sp = 0; sp < SPLIT; sp++)
            t += g_ks_part[((long)sp * BH + bh) * 64 + tid];
        g_ks[(long)bh * 64 + tid] = t;
    }
}

// ---------------------------------------------------------------------------
// Pass 2: out_l = (phi(q_l) . KV) * z_l. 1024 blocks, one head x 512 rows,
// pipelined 128-row windows with anti-phase warps.
// smem floats: kvd[64*128] 8192 | qT[2][64*130] 16640 | z[2][128] | ks[64]
// = 25152 floats = 100608 B
// ---------------------------------------------------------------------------
__global__ void __launch_bounds__(256, 2) k_pass2(const float* __restrict__ Qin,
                                                  float* __restrict__ Out,
                                                  const float* __restrict__ D1) {
    extern __shared__ __align__(16) float sm2[];
    float* s_kvd = sm2;              // 8192 (dup pairs, perm)
    float* s_qT  = sm2 + 8192;       // 2 x 8320: [e][row], stride 130
    float* s_z   = sm2 + 24832;      // 2 x 128
    float* s_ks  = sm2 + 25088;      // 64

    const int bh = blockIdx.x >> 3, chunk = blockIdx.x & 7;
    const int b = bh >> 4, h = bh & 15;
    const int tid = threadIdx.x, w = tid >> 5, lane = tid & 31;
    const int sub = lane >> 3, p = lane & 7;
    const int rg = tid >> 3, dg = tid & 7;   // GEMM: rows 4rg..4rg+3, d 8dg..+7
    const float invT = 1.0f / log1pf(__expf(*D1));
    const float* Qb = Qin + (long)b * Ll * RS + h * Ee + (long)chunk * CH2 * RS;
    float*       Ob = Out + (long)b * Ll * RS + h * Ee + (long)chunk * CH2 * RS;

    // prologue loads
    float ksr = 0.f;
    if (tid < 64) ksr = g_ks[(long)bh * 64 + tid];
    float4 kvr[4];
    {
        const float* kvsrc = g_kv + (long)bh * 4096;
        #pragma unroll
        for (int c = 0; c < 4; c++)
            kvr[c] = *(const float4*)(kvsrc + (tid + 256 * c) * 4);
    }
    if (tid < 64) s_ks[tid] = ksr;
    __syncthreads();

    float myks[8];
    {
        float4 kA = *(const float4*)(s_ks + 8 * p);
        float4 kB = *(const float4*)(s_ks + 8 * p + 4);
        myks[0] = kA.x; myks[1] = kA.y; myks[2] = kA.z; myks[3] = kA.w;
        myks[4] = kB.x; myks[5] = kB.y; myks[6] = kB.z; myks[7] = kB.w;
    }

    auto softmax2 = [&](int tile) {
        const float* qsrc = Qb + (long)tile * T2 * RS;
        float* qb = s_qT + (tile & 1) * 8320;
        float* zb = s_z + (tile & 1) * 128;
        #pragma unroll
        for (int it = 0; it < 4; it++) {
            const int r = w * 16 + it * 4 + sub;
            const float* qp = qsrc + (long)r * RS + 8 * p;
            float4 A = *(const float4*)qp;
            float4 B = *(const float4*)(qp + 4);
            float e0 = __expf((A.x < 0.f ? NEG_CLAMP : A.x) * invT);
            float e1 = __expf((A.y < 0.f ? NEG_CLAMP : A.y) * invT);
            float e2 = __expf((A.z < 0.f ? NEG_CLAMP : A.z) * invT);
            float e3 = __expf((A.w < 0.f ? NEG_CLAMP : A.w) * invT);
            float e4 = __expf((B.x < 0.f ? NEG_CLAMP : B.x) * invT);
            float e5 = __expf((B.y < 0.f ? NEG_CLAMP : B.y) * invT);
            float e6 = __expf((B.z < 0.f ? NEG_CLAMP : B.z) * invT);
            float e7 = __expf((B.w < 0.f ? NEG_CLAMP : B.w) * invT);
            float ls = ((e0 + e1) + (e2 + e3)) + ((e4 + e5) + (e6 + e7));
            float dt = ((e0 * myks[0] + e1 * myks[1]) + (e2 * myks[2] + e3 * myks[3]))
                     + ((e4 * myks[4] + e5 * myks[5]) + (e6 * myks[6] + e7 * myks[7]));
            #pragma unroll
            for (int o = 1; o <= 4; o <<= 1) {
                ls += __shfl_xor_sync(0xffffffffu, ls, o);
                dt += __shfl_xor_sync(0xffffffffu, dt, o);
            }
            float rs = 1.0f / ls;
            float zz = 1.0f / (dt * rs + EPSV);
            e0 *= rs; e1 *= rs; e2 *= rs; e3 *= rs;
            e4 *= rs; e5 *= rs; e6 *= rs; e7 *= rs;
            qb[(8 * p + 0) * 130 + r] = e0;
            qb[(8 * p + 1) * 130 + r] = e1;
            qb[(8 * p + 2) * 130 + r] = e2;
            qb[(8 * p + 3) * 130 + r] = e3;
            qb[(8 * p + 4) * 130 + r] = e4;
            qb[(8 * p + 5) * 130 + r] = e5;
            qb[(8 * p + 6) * 130 + r] = e6;
            qb[(8 * p + 7) * 130 + r] = e7;
            if (p == 0) zb[r] = zz;
        }
    };

    auto gemm2 = [&](int tile) {
        const float* qb = s_qT + (tile & 1) * 8320;
        const float* zb = s_z + (tile & 1) * 128;
        u64 acc[2][8];
        #pragma unroll
        for (int q = 0; q < 2; q++)
            #pragma unroll
            for (int j = 0; j < 8; j++) acc[q][j] = 0ull;
        #pragma unroll 2
        for (int e = 0; e < 64; e++) {
            const float* qc = qb + e * 130 + 4 * rg;
            u64 q0 = *(const u64*)(qc);       // rows 4rg, 4rg+1
            u64 q1 = *(const u64*)(qc + 2);   // rows 4rg+2, 4rg+3
            const float* kr = s_kvd + e * 128;
            ulonglong2 k0 = *(const ulonglong2*)(kr + 4 * dg);
            ulonglong2 k1 = *(const ulonglong2*)(kr + 32 + 4 * dg);
            ulonglong2 k2 = *(const ulonglong2*)(kr + 64 + 4 * dg);
            ulonglong2 k3 = *(const ulonglong2*)(kr + 96 + 4 * dg);
            u64 kd[8] = {k0.x, k0.y, k1.x, k1.y, k2.x, k2.y, k3.x, k3.y};
            #pragma unroll
            for (int j = 0; j < 8; j++) {
                acc[0][j] = ffma2(q0, kd[j], acc[0][j]);
                acc[1][j] = ffma2(q1, kd[j], acc[1][j]);
            }
        }
        #pragma unroll
        for (int q = 0; q < 2; q++) {
            const int r0 = 4 * rg + 2 * q;
            const u64 zp = pack2(zb[r0], zb[r0 + 1]);
            float2 sc[8];
            #pragma unroll
            for (int j = 0; j < 8; j++) sc[j] = unpack2(fmul2(acc[q][j], zp));
            float* oA = Ob + (long)(tile * T2 + r0) * RS + 8 * dg;
            *(float4*)(oA)     = make_float4(sc[0].x, sc[1].x, sc[2].x, sc[3].x);
            *(float4*)(oA + 4) = make_float4(sc[4].x, sc[5].x, sc[6].x, sc[7].x);
            float* oB = oA + RS;
            *(float4*)(oB)     = make_float4(sc[0].y, sc[1].y, sc[2].y, sc[3].y);
            *(float4*)(oB + 4) = make_float4(sc[4].y, sc[5].y, sc[6].y, sc[7].y);
        }
    };

    // stage KV duplicated+permuted; softmax tile 0
    #pragma unroll
    for (int c = 0; c < 4; c++) {
        int i4 = tid + 256 * c;
        int e = i4 >> 4, d0 = (i4 & 15) * 4;
        float* rowb = s_kvd + e * 128;
        *(u64*)(rowb + doff(d0 + 0)) = pack2(kvr[c].x, kvr[c].x);
        *(u64*)(rowb + doff(d0 + 1)) = pack2(kvr[c].y, kvr[c].y);
        *(u64*)(rowb + doff(d0 + 2)) = pack2(kvr[c].z, kvr[c].z);
        *(u64*)(rowb + doff(d0 + 3)) = pack2(kvr[c].w, kvr[c].w);
    }
    softmax2(0);
    __syncthreads();

    for (int t = 0; t < NT2; t++) {
        if (w & 1) {
            gemm2(t);
            if (t + 1 < NT2) softmax2(t + 1);
        } else {
            if (t + 1 < NT2) softmax2(t + 1);
            gemm2(t);
        }
        __syncthreads();
    }
}

extern "C" void kernel_launch(void* const* d_in, const int* in_sizes, int n_in,
                              void* d_out, int out_size) {
    const float* Q  = (const float*)d_in[0];
    const float* K  = (const float*)d_in[1];
    const float* V  = (const float*)d_in[2];
    const float* D1 = (const float*)d_in[3];
    float* O = (float*)d_out;

    const int smem1 = 20992 * 4;  // 83968 B
    const int smem2 = 25152 * 4;  // 100608 B
    cudaFuncSetAttribute(k_pass1, cudaFuncAttributeMaxDynamicSharedMemorySize, smem1);
    cudaFuncSetAttribute(k_pass2, cudaFuncAttributeMaxDynamicSharedMemorySize, smem2);

    k_pass1 <<<BH * SPLIT, 256, smem1>>>(K, V, D1);
    k_reduce<<<BH * 4, 256>>>();
    k_pass2 <<<BH * 8, 256, smem2>>>(Q, O, D1);
}

// round 9
// speedup vs baseline: 1.8875x; 1.2924x over previous
#include <cuda_runtime.h>
#include <cstdint>

#define NEG_CLAMP -20.0f
#define EPSV 1e-6f

static constexpr int Ll = 4096, Hh = 16, Ee = 64;
static constexpr int BH = 128;             // B*H
static constexpr int RS = Hh * Ee;         // 1024 floats per L-row
static constexpr int SPLIT = 8;
static constexpr int ROWS1 = Ll / SPLIT;   // 512
static constexpr int TILE = 64;            // pass-1 window rows
static constexpr int NT1 = ROWS1 / TILE;   // 8
static constexpr int CH2 = 512;            // pass-2 rows per block
static constexpr int T2 = 128;             // pass-2 window rows
static constexpr int NT2 = CH2 / T2;       // 4

__device__ float g_kv_part[SPLIT * BH * Ee * Ee];
__device__ float g_ks_part[SPLIT * BH * Ee];
__device__ float g_kv[BH * Ee * Ee];
__device__ float g_ks[BH * Ee];

typedef unsigned long long u64;

__device__ __forceinline__ u64 pack2(float x, float y) {
    u64 r; asm("mov.b64 %0, {%1, %2};" : "=l"(r) : "f"(x), "f"(y)); return r;
}
__device__ __forceinline__ float2 unpack2(u64 v) {
    float2 r; asm("mov.b64 {%0, %1}, %2;" : "=f"(r.x), "=f"(r.y) : "l"(v)); return r;
}
__device__ __forceinline__ u64 ffma2(u64 a, u64 b, u64 c) {
    u64 d; asm("fma.rn.f32x2 %0, %1, %2, %3;" : "=l"(d) : "l"(a), "l"(b), "l"(c)); return d;
}
__device__ __forceinline__ u64 fmul2(u64 a, u64 b) {
    u64 d; asm("mul.rn.f32x2 %0, %1, %2;" : "=l"(d) : "l"(a), "l"(b)); return d;
}
__device__ __forceinline__ void cpa16(uint32_t dst, const float* src) {
    asm volatile("cp.async.cg.shared.global [%0], [%1], 16;" :: "r"(dst), "l"(src));
}
#define CP_COMMIT() asm volatile("cp.async.commit_group;")
#define CP_WAIT1()  asm volatile("cp.async.wait_group 1;")

// named producer/consumer barriers (id 0 reserved for __syncthreads)
#define BAR_SYNC(id)   asm volatile("bar.sync %0, 256;"   :: "r"(id) : "memory")
#define BAR_ARRIVE(id) asm volatile("bar.arrive %0, 256;" :: "r"(id) : "memory")
// consumer-only barrier: orders ALL consumers' cp.async completions before reads
#define BAR_CONS()     asm volatile("bar.sync 5, 128;" ::: "memory")
#define FULLB(s)  (1 + (s))
#define EMPTYB(s) (3 + (s))

// Dup-pair row layout (stride 132 floats, 16B-aligned rows; 32 chunks used).
// Pair (column) c = 8p+i lives at float 32*(i>>1) + 4p + 2*(i&1).
// Consumer LDS.128 at 32j + 4g returns pairs (8g+2j, 8g+2j+1) — few distinct
// 16B words per warp, conflict-free broadcast.

// ---------------------------------------------------------------------------
// Pass 1: KV_partial = phi(K)^T V per (head, L-split) + ksum_partial.
// Warps 0-3: softmax producers (LDG K, MUFU, SHFL, STS phi-dup).
// Warps 4-7: GEMM consumers (cp.async V ring, LDS, FFMA2). Full contraction.
// smem floats: v[2][4096]=8192 | phi[2][64*132]=16896 | kst[1024] = 26112
// ---------------------------------------------------------------------------
__global__ void __launch_bounds__(256, 2) k_pass1(const float* __restrict__ Kin,
                                                  const float* __restrict__ Vin,
                                                  const float* __restrict__ D1) {
    extern __shared__ __align__(16) float sm1[];
    float* s_v   = sm1;             // 2 x 4096
    float* s_phi = sm1 + 8192;      // 2 x 8448 (dup pairs, stride 132)
    float* s_kst = sm1 + 25088;     // 16 x 64
    const uint32_t sb = (uint32_t)__cvta_generic_to_shared(sm1);

    const int bh = blockIdx.x / SPLIT, sp = blockIdx.x % SPLIT;
    const int b = bh >> 4, h = bh & 15;
    const int tid = threadIdx.x, w = tid >> 5, lane = tid & 31;
    const float invT = 1.0f / log1pf(__expf(*D1));
    const float* Kb = Kin + (long)b * Ll * RS + h * Ee + (long)sp * ROWS1 * RS;
    const float* Vb = Vin + (long)b * Ll * RS + h * Ee + (long)sp * ROWS1 * RS;

    if (w < 4) {
        // ================= producers =================
        const int sub = lane >> 3, p = lane & 7;    // 8 lanes per row
        float ksl[8];
        #pragma unroll
        for (int i = 0; i < 8; i++) ksl[i] = 0.f;

        for (int t = 0; t < NT1; t++) {
            if (t >= 2) BAR_SYNC(EMPTYB(t & 1));
            float* phib = s_phi + (t & 1) * 8448;
            const float* ksrc = Kb + (long)t * TILE * RS;
            float4 RA[4], RB[4];
            #pragma unroll
            for (int it = 0; it < 4; it++) {
                const float* kp = ksrc + (long)(w * 16 + it * 4 + sub) * RS + 8 * p;
                RA[it] = *(const float4*)kp;
                RB[it] = *(const float4*)(kp + 4);
            }
            #pragma unroll
            for (int it = 0; it < 4; it++) {
                const int r = w * 16 + it * 4 + sub;
                float e0 = __expf((RA[it].x < 0.f ? NEG_CLAMP : RA[it].x) * invT);
                float e1 = __expf((RA[it].y < 0.f ? NEG_CLAMP : RA[it].y) * invT);
                float e2 = __expf((RA[it].z < 0.f ? NEG_CLAMP : RA[it].z) * invT);
                float e3 = __expf((RA[it].w < 0.f ? NEG_CLAMP : RA[it].w) * invT);
                float e4 = __expf((RB[it].x < 0.f ? NEG_CLAMP : RB[it].x) * invT);
                float e5 = __expf((RB[it].y < 0.f ? NEG_CLAMP : RB[it].y) * invT);
                float e6 = __expf((RB[it].z < 0.f ? NEG_CLAMP : RB[it].z) * invT);
                float e7 = __expf((RB[it].w < 0.f ? NEG_CLAMP : RB[it].w) * invT);
                float ls = ((e0 + e1) + (e2 + e3)) + ((e4 + e5) + (e6 + e7));
                ls += __shfl_xor_sync(0xffffffffu, ls, 1);
                ls += __shfl_xor_sync(0xffffffffu, ls, 2);
                ls += __shfl_xor_sync(0xffffffffu, ls, 4);
                float rs = 1.0f / ls;
                e0 *= rs; e1 *= rs; e2 *= rs; e3 *= rs;
                e4 *= rs; e5 *= rs; e6 *= rs; e7 *= rs;
                ksl[0] += e0; ksl[1] += e1; ksl[2] += e2; ksl[3] += e3;
                ksl[4] += e4; ksl[5] += e5; ksl[6] += e6; ksl[7] += e7;
                float* pr = phib + r * 132 + 4 * p;
                *(u64*)(pr)      = pack2(e0, e0);
                *(u64*)(pr + 2)  = pack2(e1, e1);
                *(u64*)(pr + 32) = pack2(e2, e2);
                *(u64*)(pr + 34) = pack2(e3, e3);
                *(u64*)(pr + 64) = pack2(e4, e4);
                *(u64*)(pr + 66) = pack2(e5, e5);
                *(u64*)(pr + 96) = pack2(e6, e6);
                *(u64*)(pr + 98) = pack2(e7, e7);
            }
            BAR_ARRIVE(FULLB(t & 1));
        }
        // stage ksum partials (own buffer; no ring conflict)
        float* kr = s_kst + (w * 4 + sub) * 64 + 8 * p;
        *(float4*)(kr)     = make_float4(ksl[0], ksl[1], ksl[2], ksl[3]);
        *(float4*)(kr + 4) = make_float4(ksl[4], ksl[5], ksl[6], ksl[7]);
    } else {
        // ================= consumers =================
        const int cw = tid & 127;
        const int eg = cw >> 4, dgi = cw & 15;   // e 8eg..+7, d 4dgi..+3
        u64 acc[8][2];
        #pragma unroll
        for (int i = 0; i < 8; i++) { acc[i][0] = 0ull; acc[i][1] = 0ull; }

        auto issue_copy = [&](int tile) {
            if (tile < NT1) {
                const float* vsrc = Vb + (long)tile * TILE * RS;
                const uint32_t vd = sb + (uint32_t)((tile & 1) * 4096) * 4u;
                #pragma unroll
                for (int c = 0; c < 8; c++) {
                    int lin = cw + 128 * c;
                    int r = lin >> 4, k = lin & 15;
                    cpa16(vd + (uint32_t)(r * 64 + k * 4) * 4u,
                          vsrc + (long)r * RS + k * 4);
                }
            }
            CP_COMMIT();
        };

        issue_copy(0);

        for (int t = 0; t < NT1; t++) {
            BAR_SYNC(FULLB(t & 1));   // phi(t) ready; all consumers past gemm(t-1)
            issue_copy(t + 1);        // slot (t+1)&1 free (gemm(t-1) done by all)
            CP_WAIT1();               // OWN copies of v(t) landed
            BAR_CONS();               // ALL consumers' copies of v(t) landed
            const float* vt = s_v + (t & 1) * 4096;
            const float* pb = s_phi + (t & 1) * 8448;
            #pragma unroll 4
            for (int r = 0; r < TILE; r++) {
                const float* pr = pb + r * 132 + 4 * eg;
                ulonglong2 P0 = *(const ulonglong2*)(pr);
                ulonglong2 P1 = *(const ulonglong2*)(pr + 32);
                ulonglong2 P2 = *(const ulonglong2*)(pr + 64);
                ulonglong2 P3 = *(const ulonglong2*)(pr + 96);
                u64 pe[8] = {P0.x, P0.y, P1.x, P1.y, P2.x, P2.y, P3.x, P3.y};
                ulonglong2 V = *(const ulonglong2*)(vt + r * 64 + 4 * dgi);
                #pragma unroll
                for (int i = 0; i < 8; i++) {
                    acc[i][0] = ffma2(pe[i], V.x, acc[i][0]);
                    acc[i][1] = ffma2(pe[i], V.y, acc[i][1]);
                }
            }
            BAR_ARRIVE(EMPTYB(t & 1));
        }

        // full-contraction tile: write partial KV directly (no block reduction)
        float* dst = g_kv_part + ((long)sp * BH + bh) * 4096;
        #pragma unroll
        for (int i = 0; i < 8; i++) {
            float2 a = unpack2(acc[i][0]), c = unpack2(acc[i][1]);
            *(float4*)(dst + (8 * eg + i) * 64 + 4 * dgi) = make_float4(a.x, a.y, c.x, c.y);
        }
    }

    __syncthreads();
    if (tid < 64) {
        float s = 0.f;
        #pragma unroll
        for (int i = 0; i < 16; i++) s += s_kst[i * 64 + tid];
        g_ks_part[((long)sp * BH + bh) * 64 + tid] = s;
    }
}

// ---------------------------------------------------------------------------
// Deterministic split reduction (512 blocks)
// ---------------------------------------------------------------------------
__global__ void __launch_bounds__(256) k_reduce() {
    const int bh = blockIdx.x >> 2, part = blockIdx.x & 3;
    const int tid = threadIdx.x;
    const int i4 = part * 1024 + tid * 4;
    float4 s = make_float4(0.f, 0.f, 0.f, 0.f);
    #pragma unroll
    for (int sp = 0; sp < SPLIT; sp++) {
        float4 v = *(const float4*)(g_kv_part + ((long)sp * BH + bh) * 4096 + i4);
        s.x += v.x; s.y += v.y; s.z += v.z; s.w += v.w;
    }
    *(float4*)(g_kv + (long)bh * 4096 + i4) = s;
    if (part == 0 && tid < 64) {
        float t = 0.f;
        #pragma unroll
        for (int sp = 0; sp < SPLIT; sp++)
            t += g_ks_part[((long)sp * BH + bh) * 64 + tid];
        g_ks[(long)bh * 64 + tid] = t;
    }
}

// ---------------------------------------------------------------------------
// Pass 2: out_l = (phi(q_l) . KV) * z_l. 1024 blocks, one head x 512 rows.
// Warps 0-3 produce qT (transposed) + z; warps 4-7 GEMM+store (row-pair f32x2).
// smem floats: kvd[64*128]=8192 | qT[2][64*130]=16640 | z[2][128] | ks[64]
// ---------------------------------------------------------------------------
__global__ void __launch_bounds__(256, 2) k_pass2(const float* __restrict__ Qin,
                                                  float* __restrict__ Out,
                                                  const float* __restrict__ D1) {
    extern __shared__ __align__(16) float sm2[];
    float* s_kvd = sm2;              // 8192 (dup pairs, stride 128)
    float* s_qT  = sm2 + 8192;       // 2 x 8320: [e][row], stride 130
    float* s_z   = sm2 + 24832;      // 2 x 128
    float* s_ks  = sm2 + 25088;      // 64

    const int bh = blockIdx.x >> 3, chunk = blockIdx.x & 7;
    const int b = bh >> 4, h = bh & 15;
    const int tid = threadIdx.x, w = tid >> 5, lane = tid & 31;
    const float invT = 1.0f / log1pf(__expf(*D1));
    const float* Qb = Qin + (long)b * Ll * RS + h * Ee + (long)chunk * CH2 * RS;
    float*       Ob = Out + (long)b * Ll * RS + h * Ee + (long)chunk * CH2 * RS;

    // stage KV duplicated + ksum (all threads), then diverge into roles
    {
        const float* kvsrc = g_kv + (long)bh * 4096;
        #pragma unroll
        for (int c = 0; c < 4; c++) {
            int i4 = tid + 256 * c;
            float4 v4 = *(const float4*)(kvsrc + i4 * 4);
            int e = i4 >> 4, d0 = (i4 & 15) * 4;
            // dup pair d -> float 32*((d&7)>>1) + 4*(d>>3) + 2*(d&1)
            float* rowb = s_kvd + e * 128 + 4 * (d0 >> 3);
            const int j2 = (d0 & 7) >> 1;   // 0 or 2
            *(u64*)(rowb + 32 * j2)           = pack2(v4.x, v4.x);
            *(u64*)(rowb + 32 * j2 + 2)       = pack2(v4.y, v4.y);
            *(u64*)(rowb + 32 * (j2 + 1))     = pack2(v4.z, v4.z);
            *(u64*)(rowb + 32 * (j2 + 1) + 2) = pack2(v4.w, v4.w);
        }
        if (tid < 64) s_ks[tid] = g_ks[(long)bh * 64 + tid];
    }
    __syncthreads();

    if (w < 4) {
        // ================= producers =================
        const int sub = lane >> 3, p = lane & 7;
        float myks[8];
        {
            float4 kA = *(const float4*)(s_ks + 8 * p);
            float4 kB = *(const float4*)(s_ks + 8 * p + 4);
            myks[0] = kA.x; myks[1] = kA.y; myks[2] = kA.z; myks[3] = kA.w;
            myks[4] = kB.x; myks[5] = kB.y; myks[6] = kB.z; myks[7] = kB.w;
        }
        for (int t = 0; t < NT2; t++) {
            if (t >= 2) BAR_SYNC(EMPTYB(t & 1));
            float* qb = s_qT + (t & 1) * 8320;
            float* zb = s_z + (t & 1) * 128;
            const float* qsrc = Qb + (long)t * T2 * RS;
            #pragma unroll
            for (int half = 0; half < 2; half++) {
                float4 RA[4], RB[4];
                #pragma unroll
                for (int i2 = 0; i2 < 4; i2++) {
                    const int r = w * 32 + (half * 4 + i2) * 4 + sub;
                    const float* qp = qsrc + (long)r * RS + 8 * p;
                    RA[i2] = *(const float4*)qp;
                    RB[i2] = *(const float4*)(qp + 4);
                }
                #pragma unroll
                for (int i2 = 0; i2 < 4; i2++) {
                    const int r = w * 32 + (half * 4 + i2) * 4 + sub;
                    float e0 = __expf((RA[i2].x < 0.f ? NEG_CLAMP : RA[i2].x) * invT);
                    float e1 = __expf((RA[i2].y < 0.f ? NEG_CLAMP : RA[i2].y) * invT);
                    float e2 = __expf((RA[i2].z < 0.f ? NEG_CLAMP : RA[i2].z) * invT);
                    float e3 = __expf((RA[i2].w < 0.f ? NEG_CLAMP : RA[i2].w) * invT);
                    float e4 = __expf((RB[i2].x < 0.f ? NEG_CLAMP : RB[i2].x) * invT);
                    float e5 = __expf((RB[i2].y < 0.f ? NEG_CLAMP : RB[i2].y) * invT);
                    float e6 = __expf((RB[i2].z < 0.f ? NEG_CLAMP : RB[i2].z) * invT);
                    float e7 = __expf((RB[i2].w < 0.f ? NEG_CLAMP : RB[i2].w) * invT);
                    float ls = ((e0 + e1) + (e2 + e3)) + ((e4 + e5) + (e6 + e7));
                    float dt = ((e0 * myks[0] + e1 * myks[1]) + (e2 * myks[2] + e3 * myks[3]))
                             + ((e4 * myks[4] + e5 * myks[5]) + (e6 * myks[6] + e7 * myks[7]));
                    #pragma unroll
                    for (int o = 1; o <= 4; o <<= 1) {
                        ls += __shfl_xor_sync(0xffffffffu, ls, o);
                        dt += __shfl_xor_sync(0xffffffffu, dt, o);
                    }
                    float rs = 1.0f / ls;
                    float zz = 1.0f / (dt * rs + EPSV);
                    e0 *= rs; e1 *= rs; e2 *= rs; e3 *= rs;
                    e4 *= rs; e5 *= rs; e6 *= rs; e7 *= rs;
                    qb[(8 * p + 0) * 130 + r] = e0;
                    qb[(8 * p + 1) * 130 + r] = e1;
                    qb[(8 * p + 2) * 130 + r] = e2;
                    qb[(8 * p + 3) * 130 + r] = e3;
                    qb[(8 * p + 4) * 130 + r] = e4;
                    qb[(8 * p + 5) * 130 + r] = e5;
                    qb[(8 * p + 6) * 130 + r] = e6;
                    qb[(8 * p + 7) * 130 + r] = e7;
                    if (p == 0) zb[r] = zz;
                }
            }
            BAR_ARRIVE(FULLB(t & 1));
        }
    } else {
        // ================= consumers =================
        const int cw = tid & 127;
        const int rg = cw >> 3, dg = cw & 7;   // rows 8rg..+7, d 8dg..+7
        for (int t = 0; t < NT2; t++) {
            BAR_SYNC(FULLB(t & 1));
            const float* qb = s_qT + (t & 1) * 8320;
            const float* zb = s_z + (t & 1) * 128;
            u64 acc[4][8];
            #pragma unroll
            for (int pr = 0; pr < 4; pr++)
                #pragma unroll
                for (int j = 0; j < 8; j++) acc[pr][j] = 0ull;
            #pragma unroll 2
            for (int e = 0; e < Ee; e++) {
                const float* qc = qb + e * 130 + 8 * rg;
                u64 q0 = *(const u64*)(qc);
                u64 q1 = *(const u64*)(qc + 2);
                u64 q2 = *(const u64*)(qc + 4);
                u64 q3 = *(const u64*)(qc + 6);
                const float* kr = s_kvd + e * 128 + 4 * dg;
                ulonglong2 K0 = *(const ulonglong2*)(kr);
                ulonglong2 K1 = *(const ulonglong2*)(kr + 32);
                ulonglong2 K2 = *(const ulonglong2*)(kr + 64);
                ulonglong2 K3 = *(const ulonglong2*)(kr + 96);
                u64 kd[8] = {K0.x, K0.y, K1.x, K1.y, K2.x, K2.y, K3.x, K3.y};
                #pragma unroll
                for (int j = 0; j < 8; j++) {
                    acc[0][j] = ffma2(q0, kd[j], acc[0][j]);
                    acc[1][j] = ffma2(q1, kd[j], acc[1][j]);
                    acc[2][j] = ffma2(q2, kd[j], acc[2][j]);
                    acc[3][j] = ffma2(q3, kd[j], acc[3][j]);
                }
            }
            #pragma unroll
            for (int pr = 0; pr < 4; pr++) {
                const int r0 = 8 * rg + 2 * pr;
                const u64 zp = pack2(zb[r0], zb[r0 + 1]);
                float2 sc[8];
                #pragma unroll
                for (int j = 0; j < 8; j++) sc[j] = unpack2(fmul2(acc[pr][j], zp));
                float* oA = Ob + (long)(t * T2 + r0) * RS + 8 * dg;
                *(float4*)(oA)     = make_float4(sc[0].x, sc[1].x, sc[2].x, sc[3].x);
                *(float4*)(oA + 4) = make_float4(sc[4].x, sc[5].x, sc[6].x, sc[7].x);
                float* oB = oA + RS;
                *(float4*)(oB)     = make_float4(sc[0].y, sc[1].y, sc[2].y, sc[3].y);
                *(float4*)(oB + 4) = make_float4(sc[4].y, sc[5].y, sc[6].y, sc[7].y);
            }
            BAR_ARRIVE(EMPTYB(t & 1));
        }
    }
}

extern "C" void kernel_launch(void* const* d_in, const int* in_sizes, int n_in,
                              void* d_out, int out_size) {
    const float* Q  = (const float*)d_in[0];
    const float* K  = (const float*)d_in[1];
    const float* V  = (const float*)d_in[2];
    const float* D1 = (const float*)d_in[3];
    float* O = (float*)d_out;

    const int smem1 = 26112 * 4;  // 104448 B
    const int smem2 = 25152 * 4;  // 100608 B
    cudaFuncSetAttribute(k_pass1, cudaFuncAttributeMaxDynamicSharedMemorySize, smem1);
    cudaFuncSetAttribute(k_pass2, cudaFuncAttributeMaxDynamicSharedMemorySize, smem2);

    k_pass1 <<<BH * SPLIT, 256, smem1>>>(K, V, D1);
    k_reduce<<<BH * 4, 256>>>();
    k_pass2 <<<BH * 8, 256, smem2>>>(Q, O, D1);
}